// round 2
// baseline (speedup 1.0000x reference)
#include <cuda_runtime.h>
#include <cstdint>

// FieldAwareFM: B=16384 samples, F=10 fields, D=8 factor dim.
// y[b] = b_lin + sum_f w[xoff[b,f]] + sum_{f<g} <emb[f, xoff[b,g]], emb[g, xoff[b,f]]>
//
// One warp per sample. Lanes 0..9 own x_off for field==lane (broadcast via shfl
// with dynamic src lane). Each lane computes pair `lane`, lanes 0..12 also pair
// lane+32. All gathers are 32B-aligned float4-pairs -> 1 L2 sector each.

#define BATCH      16384
#define NUM_FIELDS 10
#define FACTOR_DIM 8
#define INPUT_DIM  188610
#define NPAIRS     45

__constant__ int c_off[NUM_FIELDS] = {
    0, 100000, 150000, 170000, 180000, 185000, 187000, 188000, 188500, 188600
};

// Pairs (f,g), f<g, enumerated f-major.
__constant__ signed char c_pf[NPAIRS] = {
    0,0,0,0,0,0,0,0,0,
    1,1,1,1,1,1,1,1,
    2,2,2,2,2,2,2,
    3,3,3,3,3,3,
    4,4,4,4,4,
    5,5,5,5,
    6,6,6,
    7,7,
    8
};
__constant__ signed char c_pg[NPAIRS] = {
    1,2,3,4,5,6,7,8,9,
    2,3,4,5,6,7,8,9,
    3,4,5,6,7,8,9,
    4,5,6,7,8,9,
    5,6,7,8,9,
    6,7,8,9,
    7,8,9,
    8,9,
    9
};

__device__ __forceinline__ float dot8(const float4& a0, const float4& a1,
                                      const float4& b0, const float4& b1) {
    return a0.x * b0.x + a0.y * b0.y + a0.z * b0.z + a0.w * b0.w
         + a1.x * b1.x + a1.y * b1.y + a1.z * b1.z + a1.w * b1.w;
}

__global__ __launch_bounds__(256) void ffm_kernel(
    const int*   __restrict__ x,       // (B, 10) int32 per-field raw indices
    const float* __restrict__ w,       // (INPUT_DIM,)
    const float* __restrict__ blin,    // scalar
    const float* __restrict__ emb,     // (10, INPUT_DIM, 8)
    float*       __restrict__ out)     // (B,)
{
    const unsigned FULL = 0xFFFFFFFFu;
    int gtid = blockIdx.x * blockDim.x + threadIdx.x;
    int b    = gtid >> 5;           // warp index == sample index
    int lane = threadIdx.x & 31;
    if (b >= BATCH) return;

    // Lanes 0..9 load their field's global index; also gather linear weight.
    int xo = 0;
    float acc = 0.0f;
    if (lane < NUM_FIELDS) {
        xo = x[b * NUM_FIELDS + lane] + c_off[lane];
        acc = w[xo];
    }

    // ---- pair #1: p = lane (always < 45 since lane < 32) ----
    {
        int f = c_pf[lane];
        int g = c_pg[lane];
        int ig  = __shfl_sync(FULL, xo, g);   // x_off[g]
        int iff = __shfl_sync(FULL, xo, f);   // x_off[f]
        const float4* vf = reinterpret_cast<const float4*>(
            emb + ((size_t)f * INPUT_DIM + (size_t)ig) * FACTOR_DIM);
        const float4* vg = reinterpret_cast<const float4*>(
            emb + ((size_t)g * INPUT_DIM + (size_t)iff) * FACTOR_DIM);
        float4 a0 = vf[0], a1 = vf[1];
        float4 b0 = vg[0], b1 = vg[1];
        acc += dot8(a0, a1, b0, b1);
    }

    // ---- pair #2: p = lane + 32, valid for lanes 0..12 ----
    {
        int p  = lane + 32;
        int pc = (p < NPAIRS) ? p : 0;        // clamp so shuffles stay convergent
        int f = c_pf[pc];
        int g = c_pg[pc];
        int ig  = __shfl_sync(FULL, xo, g);
        int iff = __shfl_sync(FULL, xo, f);
        if (p < NPAIRS) {
            const float4* vf = reinterpret_cast<const float4*>(
                emb + ((size_t)f * INPUT_DIM + (size_t)ig) * FACTOR_DIM);
            const float4* vg = reinterpret_cast<const float4*>(
                emb + ((size_t)g * INPUT_DIM + (size_t)iff) * FACTOR_DIM);
            float4 a0 = vf[0], a1 = vf[1];
            float4 b0 = vg[0], b1 = vg[1];
            acc += dot8(a0, a1, b0, b1);
        }
    }

    // ---- warp reduction ----
    #pragma unroll
    for (int o = 16; o > 0; o >>= 1)
        acc += __shfl_xor_sync(FULL, acc, o);

    if (lane == 0)
        out[b] = acc + blin[0];
}

extern "C" void kernel_launch(void* const* d_in, const int* in_sizes, int n_in,
                              void* d_out, int out_size) {
    const int*   x    = (const int*)  d_in[0];   // (16384, 10) int32
    const float* w    = (const float*)d_in[1];   // (188610,)
    const float* blin = (const float*)d_in[2];   // scalar
    const float* emb  = (const float*)d_in[3];   // (10, 188610, 8)
    float* out = (float*)d_out;

    const int threads = 256;                      // 8 warps = 8 samples / block
    const int blocks  = (BATCH * 32) / threads;   // 2048
    ffm_kernel<<<blocks, threads>>>(x, w, blin, emb, out);
}

// round 3
// speedup vs baseline: 1.4812x; 1.4812x over previous
#include <cuda_runtime.h>
#include <cstdint>

// FieldAwareFM: B=16384, F=10 fields, D=8.
// y[b] = b_lin + sum_f w[xoff[b,f]] + sum_{f<g} <emb[f, xoff[b,g]], emb[g, xoff[b,f]]>
//
// One warp per sample. 90 quarter-tasks per sample: task t = (pair p = t>>1,
// half part = t&1). Lane loads 16B of each of the pair's two rows and dot4s.
// Adjacent lanes (2i, 2i+1) share p with parts 0/1 -> their 16B loads hit the
// SAME 32B sector within one LDG instruction (halves L1tex wavefront traffic
// vs loading whole 32B rows per lane as two separate instructions).

#define BATCH      16384
#define NUM_FIELDS 10
#define FACTOR_DIM 8
#define INPUT_DIM  188610
#define NPAIRS     45

__constant__ int c_off[NUM_FIELDS] = {
    0, 100000, 150000, 170000, 180000, 185000, 187000, 188000, 188500, 188600
};

__global__ __launch_bounds__(256, 6) void ffm_kernel(
    const int*   __restrict__ x,       // (B, 10) int32
    const float* __restrict__ w,       // (INPUT_DIM,)
    const float* __restrict__ blin,    // scalar
    const float* __restrict__ emb,     // (10, INPUT_DIM, 8)
    float*       __restrict__ out)     // (B,)
{
    const unsigned FULL = 0xFFFFFFFFu;
    int b    = (blockIdx.x * blockDim.x + threadIdx.x) >> 5;
    int lane = threadIdx.x & 31;
    if (b >= BATCH) return;

    // Lanes 0..9 own x_off for their field + gather the linear weight.
    int   xo  = 0;
    float acc = 0.0f;
    if (lane < NUM_FIELDS) {
        xo  = x[b * NUM_FIELDS + lane] + c_off[lane];
        acc = w[xo];
    }

    float4 va[3], vb[3];
    bool   valid[3];

    #pragma unroll
    for (int k = 0; k < 3; k++) {
        int  t = lane + 32 * k;            // task id 0..95 (90 valid)
        bool v = t < 2 * NPAIRS;
        int  p    = v ? (t >> 1) : 0;      // pair id 0..44 (clamped for shfl convergence)
        int  part = t & 1;                 // which 16B half of the rows

        // Triangular decode of pair p -> (f, g), f < g.
        // Boundaries land on exact perfect squares: fp32 sqrt is exact there.
        float s = sqrtf((float)(361 - 8 * p));
        int   f = (int)((19.0f - s) * 0.5f);
        int   g = p - (f * (19 - f)) / 2 + f + 1;

        int ig  = __shfl_sync(FULL, xo, g);   // x_off[g]
        int iff = __shfl_sync(FULL, xo, f);   // x_off[f]

        const float4* A = reinterpret_cast<const float4*>(
            emb + ((size_t)f * INPUT_DIM + (size_t)ig) * FACTOR_DIM) + part;
        const float4* B = reinterpret_cast<const float4*>(
            emb + ((size_t)g * INPUT_DIM + (size_t)iff) * FACTOR_DIM) + part;

        valid[k] = v;
        if (v) { va[k] = *A; vb[k] = *B; }
    }

    #pragma unroll
    for (int k = 0; k < 3; k++) {
        if (valid[k]) {
            acc += va[k].x * vb[k].x + va[k].y * vb[k].y
                 + va[k].z * vb[k].z + va[k].w * vb[k].w;
        }
    }

    // Warp reduction.
    #pragma unroll
    for (int o = 16; o > 0; o >>= 1)
        acc += __shfl_xor_sync(FULL, acc, o);

    if (lane == 0)
        out[b] = acc + blin[0];
}

extern "C" void kernel_launch(void* const* d_in, const int* in_sizes, int n_in,
                              void* d_out, int out_size) {
    const int*   x    = (const int*)  d_in[0];
    const float* w    = (const float*)d_in[1];
    const float* blin = (const float*)d_in[2];
    const float* emb  = (const float*)d_in[3];
    float* out = (float*)d_out;

    const int threads = 256;                      // 8 warps = 8 samples / block
    const int blocks  = (BATCH * 32) / threads;   // 2048
    ffm_kernel<<<blocks, threads>>>(x, w, blin, emb, out);
}